// round 13
// baseline (speedup 1.0000x reference)
#include <cuda_runtime.h>
#include <cuda_bf16.h>
#include <math.h>
#include <stdint.h>

// ---------------- problem constants ----------------
#define T_STEPS 600
#define BATCH   64
#define HID     40
#define IN_F    257
#define NTOK    (BATCH * T_STEPS)   // 38400
#define G3H     120                 // 3*HID
#define TWOH    80
#define KX_PAD  320                 // 257 padded to mult of 64
#define KF_PAD  768                 // 720 padded to mult of 64

// ---------------- scratch (static device memory; zero-initialized) ----------------
__device__ float g_giF[(size_t)T_STEPS * BATCH * G3H];
__device__ float g_giB[(size_t)T_STEPS * BATCH * G3H];
__device__ float g_hcat[(size_t)NTOK * TWOH];
__device__ float g_y1[(size_t)NTOK * TWOH];
__device__ unsigned g_cnt[128];      // per-chain scan progress (dir*64+b)
__device__ unsigned g_flag[600];     // per-row-tile kan1 completion
__device__ __nv_bfloat16 g_xhi[(size_t)NTOK * KX_PAD];
__device__ __nv_bfloat16 g_xlo[(size_t)NTOK * KX_PAD];
__device__ __nv_bfloat16 g_Wgh[2 * G3H * KX_PAD];
__device__ __nv_bfloat16 g_Wgl[2 * G3H * KX_PAD];
__device__ __nv_bfloat16 g_W1h[TWOH * KF_PAD];
__device__ __nv_bfloat16 g_W1l[TWOH * KF_PAD];
__device__ __nv_bfloat16 g_W2h[264 * KF_PAD];
__device__ __nv_bfloat16 g_W2l[264 * KF_PAD];

#define SMEM_SWIZZLE_128B(x) ((x) ^ (((x) >> 3) & 0x70))

__device__ __forceinline__ uint32_t smem_to_u32(const void* p) {
    uint32_t a;
    asm("{ .reg .u64 t; cvta.to.shared.u64 t, %1; cvt.u32.u64 %0, t; }" : "=r"(a) : "l"(p));
    return a;
}

// ---------------- warp MMA helpers ----------------
__device__ __forceinline__ void ldsm_x4(uint32_t* r, uint32_t addr) {
    asm volatile("ldmatrix.sync.aligned.m8n8.x4.shared.b16 {%0,%1,%2,%3}, [%4];"
                 : "=r"(r[0]), "=r"(r[1]), "=r"(r[2]), "=r"(r[3]) : "r"(addr));
}
__device__ __forceinline__ void ldsm_x2(uint32_t* r, uint32_t addr) {
    asm volatile("ldmatrix.sync.aligned.m8n8.x2.shared.b16 {%0,%1}, [%2];"
                 : "=r"(r[0]), "=r"(r[1]) : "r"(addr));
}
__device__ __forceinline__ void mma_bf16(float* c, const uint32_t* a, const uint32_t* b) {
    asm volatile("mma.sync.aligned.m16n8k16.row.col.f32.bf16.bf16.f32 "
                 "{%0,%1,%2,%3}, {%4,%5,%6,%7}, {%8,%9}, {%0,%1,%2,%3};"
                 : "+f"(c[0]), "+f"(c[1]), "+f"(c[2]), "+f"(c[3])
                 : "r"(a[0]), "r"(a[1]), "r"(a[2]), "r"(a[3]), "r"(b[0]), "r"(b[1]));
}

__device__ __forceinline__ void cp16(uint32_t saddr, const void* g) {
    asm volatile("cp.async.cg.shared.global [%0], [%1], 16;" :: "r"(saddr), "l"(g));
}
#define CP_COMMIT() asm volatile("cp.async.commit_group;" ::: "memory")
#define CP_WAIT1()  asm volatile("cp.async.wait_group 1;" ::: "memory")

__device__ __forceinline__ unsigned ld_acquire(const unsigned* p) {
    unsigned v;
    asm volatile("ld.acquire.gpu.u32 %0, [%1];" : "=r"(v) : "l"(p) : "memory");
    return v;
}
__device__ __forceinline__ void st_release(unsigned* p, unsigned v) {
    asm volatile("st.release.gpu.u32 [%0], %1;" :: "l"(p), "r"(v) : "memory");
}

__device__ __forceinline__ void split_bf16(float v, __nv_bfloat16& h, __nv_bfloat16& l) {
    h = __float2bfloat16(v);
    l = __float2bfloat16(v - __bfloat162float(h));
}

__device__ __forceinline__ float gridv(int j) { return 0.4f * (float)(j - 3) - 1.0f; }

__device__ __forceinline__ void basis8(float x, float* o) {
    float bset[11];
#pragma unroll
    for (int j = 0; j < 11; j++)
        bset[j] = (x >= gridv(j) && x < gridv(j + 1)) ? 1.0f : 0.0f;
#pragma unroll
    for (int j = 0; j < 10; j++)
        bset[j] = (x - gridv(j)) * 2.5f * bset[j] + (gridv(j + 2) - x) * 2.5f * bset[j + 1];
#pragma unroll
    for (int j = 0; j < 9; j++)
        bset[j] = (x - gridv(j)) * 1.25f * bset[j] + (gridv(j + 3) - x) * 1.25f * bset[j + 1];
#pragma unroll
    for (int j = 0; j < 8; j++)
        o[j] = (x - gridv(j)) * (1.0f / 1.2f) * bset[j] + (gridv(j + 4) - x) * (1.0f / 1.2f) * bset[j + 1];
}

// ---------------- conversion kernels ----------------
__global__ void conv_x(const float* __restrict__ x) {
    int idx = blockIdx.x * blockDim.x + threadIdx.x;
    if (idx < 128) g_cnt[idx] = 0;                 // reset sync state every launch
    else if (idx < 728) g_flag[idx - 128] = 0;
    if (idx >= NTOK * KX_PAD) return;
    int row = idx / KX_PAD, col = idx % KX_PAD;
    float v = (col < IN_F) ? x[(size_t)row * IN_F + col] : 0.0f;
    __nv_bfloat16 h, l; split_bf16(v, h, l);
    g_xhi[idx] = h; g_xlo[idx] = l;
}

__global__ void pack_weights(const float* __restrict__ f0W, const float* __restrict__ b0W,
                             const float* __restrict__ k1b, const float* __restrict__ k1s,
                             const float* __restrict__ k1c,
                             const float* __restrict__ k2b, const float* __restrict__ k2s,
                             const float* __restrict__ k2c)
{
    const int NG = 2 * G3H * KX_PAD;
    const int N1 = TWOH * KF_PAD;
    const int N2 = 264 * KF_PAD;
    int idx = blockIdx.x * blockDim.x + threadIdx.x;
    if (idx >= NG + N1 + N2) return;
    float v = 0.0f;
    if (idx < NG) {
        int d = idx / (G3H * KX_PAD), r = (idx / KX_PAD) % G3H, c = idx % KX_PAD;
        if (c < IN_F) v = d ? b0W[r * IN_F + c] : f0W[r * IN_F + c];
        __nv_bfloat16 h, l; split_bf16(v, h, l);
        g_Wgh[idx] = h; g_Wgl[idx] = l;
        return;
    }
    idx -= NG;
    if (idx < N1) {
        int o = idx / KF_PAD, k = idx % KF_PAD;
        if (k < TWOH) v = k1b[o * TWOH + k];
        else if (k < 720) {
            int e = k - TWOH, i = e >> 3, g = e & 7;
            v = k1s[(o * TWOH + i) * 8 + g] * k1c[o * TWOH + i];
        }
        __nv_bfloat16 h, l; split_bf16(v, h, l);
        g_W1h[idx] = h; g_W1l[idx] = l;
        return;
    }
    idx -= N1;
    {
        int o = idx / KF_PAD, k = idx % KF_PAD;
        if (o < IN_F) {
            if (k < TWOH) v = k2b[o * TWOH + k];
            else if (k < 720) {
                int e = k - TWOH, i = e >> 3, g = e & 7;
                v = k2s[(o * TWOH + i) * 8 + g] * k2c[o * TWOH + i];
            }
        }
        __nv_bfloat16 h, l; split_bf16(v, h, l);
        g_W2h[idx] = h; g_W2l[idx] = l;
    }
}

// ---------------- gates GEMM (R7 config, M64, 128 threads, cp.async 2-stage) ----------------
struct TGg {
    static constexpr int N128    = 120 * 128;
    static constexpr int OFF_AHI = 0;
    static constexpr int OFF_ALO = 8192;
    static constexpr int OFF_BHI = 16384;
    static constexpr int OFF_BLO = 16384 + N128;
    static constexpr int STAGE   = 16384 + 2 * N128;
    static constexpr int TOTAL   = 2 * STAGE;
};

__global__ __launch_bounds__(128) void hgemm_gates(
    const __nv_bfloat16* __restrict__ Ahi, const __nv_bfloat16* __restrict__ Alo,
    const float* __restrict__ biasF, const float* __restrict__ biasB)
{
    constexpr int NT8 = 15;   // 120/8
    extern __shared__ __align__(128) char smem[];
    const uint32_t smemB = smem_to_u32(smem);
    const int tid = threadIdx.x, wid = tid >> 5, lid = tid & 31;

    const __nv_bfloat16* Bhi = g_Wgh + (size_t)blockIdx.y * G3H * KX_PAD;
    const __nv_bfloat16* Blo = g_Wgl + (size_t)blockIdx.y * G3H * KX_PAD;
    const size_t aRow0 = (size_t)blockIdx.x * 64;

    float acc[NT8][4];
#pragma unroll
    for (int t = 0; t < NT8; t++)
#pragma unroll
        for (int j = 0; j < 4; j++) acc[t][j] = 0.0f;

    const int rwA = wid * 16 + (lid & 15);
    const int khA = lid >> 4;
    const int bTs = (lid >> 4) & 1, bKh = (lid >> 3) & 1, bRow = lid & 7;

    auto load_chunk = [&](int kc, int st) {
        const int kOff = kc << 6;
        const uint32_t base = smemB + st * TGg::STAGE;
#pragma unroll
        for (int j = 0; j < 4; j++) {
            int s = j * 128 + tid;
            int r = s >> 3, c = s & 7;
            size_t go = (aRow0 + r) * (size_t)KX_PAD + kOff + c * 8;
            uint32_t sw = SMEM_SWIZZLE_128B((uint32_t)(r * 128 + c * 16));
            cp16(base + TGg::OFF_AHI + sw, Ahi + go);
            cp16(base + TGg::OFF_ALO + sw, Alo + go);
        }
        for (int s = tid; s < 120 * 8; s += 128) {
            int r = s >> 3, c = s & 7;
            size_t go = (size_t)r * KX_PAD + kOff + c * 8;
            uint32_t sw = SMEM_SWIZZLE_128B((uint32_t)(r * 128 + c * 16));
            cp16(base + TGg::OFF_BHI + sw, Bhi + go);
            cp16(base + TGg::OFF_BLO + sw, Blo + go);
        }
    };

    const int nchunk = KX_PAD >> 6;
    load_chunk(0, 0);
    CP_COMMIT();
    for (int kc = 0; kc < nchunk; kc++) {
        if (kc + 1 < nchunk) load_chunk(kc + 1, (kc + 1) & 1);
        CP_COMMIT();
        CP_WAIT1();
        __syncthreads();
        const uint32_t base = smemB + (kc & 1) * TGg::STAGE;
#pragma unroll
        for (int ks = 0; ks < 4; ks++) {
            uint32_t ah[4], al[4];
            uint32_t offA = SMEM_SWIZZLE_128B((uint32_t)(rwA * 128 + ks * 32 + khA * 16));
            ldsm_x4(ah, base + TGg::OFF_AHI + offA);
            ldsm_x4(al, base + TGg::OFF_ALO + offA);
#pragma unroll
            for (int nt = 0; nt < NT8; nt += 2) {
                uint32_t bh[4], bl[4];
                if (nt + 1 < NT8) {
                    int n = (nt + bTs) * 8 + bRow;
                    uint32_t off = SMEM_SWIZZLE_128B((uint32_t)(n * 128 + ks * 32 + bKh * 16));
                    ldsm_x4(bh, base + TGg::OFF_BHI + off);
                    ldsm_x4(bl, base + TGg::OFF_BLO + off);
                } else {
                    int n = nt * 8 + bRow;
                    uint32_t off = SMEM_SWIZZLE_128B((uint32_t)(n * 128 + ks * 32 + bKh * 16));
                    ldsm_x2(bh, base + TGg::OFF_BHI + off);
                    ldsm_x2(bl, base + TGg::OFF_BLO + off);
                }
                mma_bf16(acc[nt], ah, bh);
                mma_bf16(acc[nt], al, bh);
                mma_bf16(acc[nt], ah, bl);
                if (nt + 1 < NT8) {
                    mma_bf16(acc[nt + 1], ah, bh + 2);
                    mma_bf16(acc[nt + 1], al, bh + 2);
                    mma_bf16(acc[nt + 1], ah, bl + 2);
                }
            }
        }
        __syncthreads();
    }

    const int r0 = (int)aRow0 + wid * 16 + (lid >> 2);
    const int cO = 2 * (lid & 3);
    float* baseO = blockIdx.y ? g_giB : g_giF;
    const float* bia = blockIdx.y ? biasB : biasF;
    int b0 = r0 / T_STEPS, t0 = r0 % T_STEPS;
    int b1 = (r0 + 8) / T_STEPS, t1 = (r0 + 8) % T_STEPS;
    float* d0 = baseO + ((size_t)t0 * BATCH + b0) * G3H;
    float* d1 = baseO + ((size_t)t1 * BATCH + b1) * G3H;
#pragma unroll
    for (int t = 0; t < NT8; t++) {
        int cb = t * 8 + cO;
        d0[cb]     = acc[t][0] + bia[cb];
        d0[cb + 1] = acc[t][1] + bia[cb + 1];
        d1[cb]     = acc[t][2] + bia[cb];
        d1[cb + 1] = acc[t][3] + bia[cb + 1];
    }
}

// ---------------- GRU helpers ----------------
__device__ __forceinline__ float sigm_fast(float x) {
    float e = __expf(-x);
    return __fdividef(1.0f, 1.0f + e);
}
__device__ __forceinline__ float tanh_fast(float x) {
    float e = __expf(2.0f * x);
    return 1.0f - __fdividef(2.0f, 1.0f + e);
}

// ================= fused kernel: scan + gated kan1 + gated kan2 =================
// smem layout for kan roles:
#define OFF_X    0        // 64x80 fp32 = 20480
#define OFF_AHI_ 20480    // 8192
#define OFF_ALO_ 28672    // 8192
#define OFF_B_   36864    // 2 stages x (hi 88*128 + lo 88*128)
#define B_STAGE_ 22528
#define B_HALF_  11264
#define SMEM_FUSED (36864 + 2 * B_STAGE_)   // 81920

// ---- scan role (R12 merged-layer scan + progress counters) ----
__device__ void scan_role(char* smem, int b, int dir,
    const float* Whh0, const float* bhh0,
    const float* W1ih, const float* W1hh, const float* b1ih, const float* b1hh)
{
    const float* gi = dir ? g_giB : g_giF;
    float* out = g_hcat + (size_t)b * T_STEPS * TWOH + dir * HID;
    const int chain = dir * BATCH + b;

    float (*s_h0)[HID] = (float(*)[HID])(smem);
    float (*s_h1)[HID] = (float(*)[HID])(smem + 2 * HID * 4);

    const int tid  = threadIdx.x;
    const int unit = tid >> 2;
    const int q    = tid & 3;
    const int k0   = q * 10;

    float wA[3][10], wI[3][10], wH[3][10];
#pragma unroll
    for (int g = 0; g < 3; g++)
#pragma unroll
        for (int k = 0; k < 10; k++) {
            wA[g][k] = Whh0[(g * HID + unit) * HID + k0 + k];
            wI[g][k] = W1ih[(g * HID + unit) * HID + k0 + k];
            wH[g][k] = W1hh[(g * HID + unit) * HID + k0 + k];
        }
    const float brz0 = bhh0[unit];
    const float brz1 = bhh0[HID + unit];
    const float bn0  = bhh0[2 * HID + unit];
    const float bR   = b1ih[unit]           + b1hh[unit];
    const float bZ   = b1ih[HID + unit]     + b1hh[HID + unit];
    const float bIN  = b1ih[2 * HID + unit];
    const float bHN  = b1hh[2 * HID + unit];

    if (tid < HID) { s_h0[0][tid] = 0.0f; s_h0[1][tid] = 0.0f;
                     s_h1[0][tid] = 0.0f; s_h1[1][tid] = 0.0f; }

    float gc0, gc1, gc2;
    {
        int grow = dir ? (T_STEPS - 1) : 0;
        const float* gp = gi + ((size_t)grow * BATCH + b) * G3H;
        gc0 = gp[unit]; gc1 = gp[HID + unit]; gc2 = gp[2 * HID + unit];
    }
    __syncthreads();

    for (int s = 0; s <= T_STEPS; s++) {
        const int cur = s & 1;
        float gn0 = 0.f, gn1 = 0.f, gn2 = 0.f;
        if (s + 1 < T_STEPS) {
            int grow = dir ? (T_STEPS - 2 - s) : (s + 1);
            const float* gp = gi + ((size_t)grow * BATCH + b) * G3H;
            gn0 = gp[unit]; gn1 = gp[HID + unit]; gn2 = gp[2 * HID + unit];
        }

        float hk[10];
        {
            const float2* h2 = (const float2*)(s_h0[cur] + k0);
#pragma unroll
            for (int k = 0; k < 5; k++) {
                float2 v = h2[k];
                hk[2 * k] = v.x; hk[2 * k + 1] = v.y;
            }
        }

        float p0 = 0.f, p1 = 0.f, p2 = 0.f;
        float pr = 0.f, pz = 0.f, pin = 0.f, phn = 0.f;
        float hh[10];
        if (s >= 1) {
            const float2* b2 = (const float2*)(s_h1[cur ^ 1] + k0);
#pragma unroll
            for (int k = 0; k < 5; k++) {
                float2 v = b2[k];
                hh[2 * k] = v.x; hh[2 * k + 1] = v.y;
            }
        } else {
#pragma unroll
            for (int k = 0; k < 10; k++) hh[k] = 0.0f;
        }

        if (s < T_STEPS) {
#pragma unroll
            for (int k = 0; k < 10; k++) {
                p0 = fmaf(wA[0][k], hk[k], p0);
                p1 = fmaf(wA[1][k], hk[k], p1);
                p2 = fmaf(wA[2][k], hk[k], p2);
            }
        }
        if (s >= 1) {
#pragma unroll
            for (int k = 0; k < 10; k++) {
                pr  = fmaf(wI[0][k], hk[k], pr);
                pz  = fmaf(wI[1][k], hk[k], pz);
                pin = fmaf(wI[2][k], hk[k], pin);
                phn = fmaf(wH[2][k], hh[k], phn);
            }
#pragma unroll
            for (int k = 0; k < 10; k++) {
                pr = fmaf(wH[0][k], hh[k], pr);
                pz = fmaf(wH[1][k], hh[k], pz);
            }
        }

        p0  += __shfl_xor_sync(0xffffffffu, p0, 1);
        p1  += __shfl_xor_sync(0xffffffffu, p1, 1);
        p2  += __shfl_xor_sync(0xffffffffu, p2, 1);
        pr  += __shfl_xor_sync(0xffffffffu, pr, 1);
        pz  += __shfl_xor_sync(0xffffffffu, pz, 1);
        pin += __shfl_xor_sync(0xffffffffu, pin, 1);
        phn += __shfl_xor_sync(0xffffffffu, phn, 1);
        p0  += __shfl_xor_sync(0xffffffffu, p0, 2);
        p1  += __shfl_xor_sync(0xffffffffu, p1, 2);
        p2  += __shfl_xor_sync(0xffffffffu, p2, 2);
        pr  += __shfl_xor_sync(0xffffffffu, pr, 2);
        pz  += __shfl_xor_sync(0xffffffffu, pz, 2);
        pin += __shfl_xor_sync(0xffffffffu, pin, 2);
        phn += __shfl_xor_sync(0xffffffffu, phn, 2);

        if (s < T_STEPS) {
            float r = sigm_fast(gc0 + p0 + brz0);
            float z = sigm_fast(gc1 + p1 + brz1);
            float n = tanh_fast(gc2 + r * (p2 + bn0));
            float hnew = (1.0f - z) * n + z * s_h0[cur][unit];
            if (q == 0) s_h0[cur ^ 1][unit] = hnew;
        }
        if (s >= 1) {
            float r = sigm_fast(pr + bR);
            float z = sigm_fast(pz + bZ);
            float n = tanh_fast(pin + bIN + r * (phn + bHN));
            float h = (1.0f - z) * n + z * s_h1[cur ^ 1][unit];
            if (q == 0) {
                s_h1[cur][unit] = h;
                out[(size_t)(s - 1) * TWOH + unit] = h;
            }
        }
        __syncthreads();
        if (tid == 0 && s && (s & 63) == 0) st_release(&g_cnt[chain], (unsigned)s);
        gc0 = gn0; gc1 = gn1; gc2 = gn2;
    }
    if (tid == 0) st_release(&g_cnt[chain], (unsigned)T_STEPS);
}

// ---- fused KAN tile (expansion in-kernel) ----
// EPI 0: write y1 + release flag; EPI 2: sigmoid -> final out
template <int N_TILE, int EPI>
__device__ void kan_tile(char* smem, int tileIdx, int ny,
                         const float* __restrict__ Xsrc,
                         const __nv_bfloat16* __restrict__ Bhi,
                         const __nv_bfloat16* __restrict__ Blo,
                         float* __restrict__ outP, const float* __restrict__ slope)
{
    constexpr int NT8 = N_TILE / 8;
    const int tid = threadIdx.x;
    const uint32_t smemB = smem_to_u32(smem);
    const int r0 = tileIdx * 64;
    float* sX = (float*)(smem + OFF_X);

    // ---- gate ----
    if (EPI == 0) {
        if (tid == 0) {
            int b0 = r0 / T_STEPS, bL = (r0 + 63) / T_STEPS, tL = (r0 + 63) % T_STEPS;
            unsigned needA = (b0 == bL) ? (unsigned)(tL + 1) : (unsigned)T_STEPS;
            while (ld_acquire(&g_cnt[b0]) < needA) __nanosleep(256);
            while (ld_acquire(&g_cnt[64 + b0]) < needA) __nanosleep(256);
            if (bL != b0) {
                unsigned needB = (unsigned)(tL + 1);
                while (ld_acquire(&g_cnt[bL]) < needB) __nanosleep(256);
                while (ld_acquire(&g_cnt[64 + bL]) < needB) __nanosleep(256);
            }
        }
    } else {
        if (tid == 0)
            while (ld_acquire(&g_flag[tileIdx]) == 0u) __nanosleep(256);
    }
    __syncthreads();

    // ---- load X tile (64 x 80 fp32) ----
    {
        const float4* src = (const float4*)(Xsrc + (size_t)r0 * TWOH);
        float4* dst = (float4*)sX;
        for (int i = tid; i < 64 * TWOH / 4; i += 160) dst[i] = src[i];
    }
    __syncthreads();

    float acc[NT8][4];
#pragma unroll
    for (int t = 0; t < NT8; t++)
#pragma unroll
        for (int j = 0; j < 4; j++) acc[t][j] = 0.0f;

    const int wid = tid >> 5, lid = tid & 31;
    const int rwA = wid * 16 + (lid & 15);
    const int khA = lid >> 4;
    const int bTs = (lid >> 4) & 1, bKh = (lid >> 3) & 1, bRow = lid & 7;

    auto loadB = [&](int kc, int st) {
        if (tid < 128) {
            const int kOff = kc << 6;
            uint32_t bHiB = smemB + OFF_B_ + st * B_STAGE_;
            for (int s = tid; s < N_TILE * 8; s += 128) {
                int r = s >> 3, c = s & 7;
                size_t go = (size_t)r * KF_PAD + kOff + c * 8;
                uint32_t sw = SMEM_SWIZZLE_128B((uint32_t)(r * 128 + c * 16));
                cp16(bHiB + sw, Bhi + go);
                cp16(bHiB + B_HALF_ + sw, Blo + go);
            }
        }
    };

    loadB(0, 0);
    CP_COMMIT();

    for (int kc = 0; kc < 12; kc++) {
        if (kc + 1 < 12) loadB(kc + 1, (kc + 1) & 1);
        CP_COMMIT();
        // ---- compute A chunk (expansion) ----
        if (tid < 128) {
            const int kOff = kc << 6;
#pragma unroll
            for (int j = 0; j < 4; j++) {
                int g = j * 128 + tid;
                int row = g >> 3, cg = g & 7;
                int c0 = kOff + cg * 8;
                union { __nv_bfloat16 b[8]; uint4 u; } hv, lv;
                if (c0 < TWOH) {
#pragma unroll
                    for (int k2 = 0; k2 < 8; k2++) {
                        float xv = sX[row * TWOH + c0 + k2];
                        float sv = xv * __fdividef(1.0f, 1.0f + __expf(-xv));
                        split_bf16(sv, hv.b[k2], lv.b[k2]);
                    }
                } else {
                    int u = (c0 - TWOH) >> 3;
                    if (u < TWOH) {
                        float xv = sX[row * TWOH + u];
                        float bs[8];
                        basis8(xv, bs);
#pragma unroll
                        for (int k2 = 0; k2 < 8; k2++) split_bf16(bs[k2], hv.b[k2], lv.b[k2]);
                    } else {
                        hv.u = make_uint4(0, 0, 0, 0);
                        lv.u = make_uint4(0, 0, 0, 0);
                    }
                }
                uint32_t sw = SMEM_SWIZZLE_128B((uint32_t)(row * 128 + cg * 16));
                *(uint4*)(smem + OFF_AHI_ + sw) = hv.u;
                *(uint4*)(smem + OFF_ALO_ + sw) = lv.u;
            }
        }
        CP_WAIT1();
        __syncthreads();

        if (tid < 128) {
            const uint32_t bHiB = smemB + OFF_B_ + (kc & 1) * B_STAGE_;
            const uint32_t bLoB = bHiB + B_HALF_;
            const uint32_t aHiB = smemB + OFF_AHI_;
            const uint32_t aLoB = smemB + OFF_ALO_;
#pragma unroll
            for (int ks = 0; ks < 4; ks++) {
                uint32_t ah[4], al[4];
                uint32_t offA = SMEM_SWIZZLE_128B((uint32_t)(rwA * 128 + ks * 32 + khA * 16));
                ldsm_x4(ah, aHiB + offA);
                ldsm_x4(al, aLoB + offA);
#pragma unroll
                for (int nt = 0; nt < NT8; nt += 2) {
                    uint32_t bh[4], bl[4];
                    if (nt + 1 < NT8) {
                        int n = (nt + bTs) * 8 + bRow;
                        uint32_t off = SMEM_SWIZZLE_128B((uint32_t)(n * 128 + ks * 32 + bKh * 16));
                        ldsm_x4(bh, bHiB + off);
                        ldsm_x4(bl, bLoB + off);
                    } else {
                        int n = nt * 8 + bRow;
                        uint32_t off = SMEM_SWIZZLE_128B((uint32_t)(n * 128 + ks * 32 + bKh * 16));
                        ldsm_x2(bh, bHiB + off);
                        ldsm_x2(bl, bLoB + off);
                    }
                    mma_bf16(acc[nt], ah, bh);
                    mma_bf16(acc[nt], al, bh);
                    mma_bf16(acc[nt], ah, bl);
                    if (nt + 1 < NT8) {
                        mma_bf16(acc[nt + 1], ah, bh + 2);
                        mma_bf16(acc[nt + 1], al, bh + 2);
                        mma_bf16(acc[nt + 1], ah, bl + 2);
                    }
                }
            }
        }
        __syncthreads();
    }

    // ---- epilogue ----
    if (tid < 128) {
        const int rr = r0 + wid * 16 + (lid >> 2);
        const int cO = 2 * (lid & 3);
        if (EPI == 0) {
#pragma unroll
            for (int t = 0; t < NT8; t++) {
                int cb = t * 8 + cO;
                float* o0 = outP + (size_t)rr * TWOH + cb;
                float* o1 = outP + (size_t)(rr + 8) * TWOH + cb;
                o0[0] = acc[t][0]; o0[1] = acc[t][1];
                o1[0] = acc[t][2]; o1[1] = acc[t][3];
            }
        } else {
            const int cbase = ny * 88;
#pragma unroll
            for (int t = 0; t < NT8; t++) {
                int cb = cbase + t * 8 + cO;
#pragma unroll
                for (int j = 0; j < 2; j++) {
                    int cg = cb + j;
                    if (cg < IN_F) {
                        outP[(size_t)rr * IN_F + cg] =
                            1.2f / (1.0f + expf(-slope[cg] * acc[t][j]));
                        outP[(size_t)(rr + 8) * IN_F + cg] =
                            1.2f / (1.0f + expf(-slope[cg] * acc[t][2 + j]));
                    }
                }
            }
        }
    }
    if (EPI == 0) {
        __syncthreads();
        if (tid == 0) st_release(&g_flag[tileIdx], 1u);
    }
}

__global__ __launch_bounds__(160) void fused_all(
    const float* __restrict__ WhhF0, const float* __restrict__ bhhF0,
    const float* __restrict__ WihF1, const float* __restrict__ WhhF1,
    const float* __restrict__ bihF1, const float* __restrict__ bhhF1,
    const float* __restrict__ WhhB0, const float* __restrict__ bhhB0,
    const float* __restrict__ WihB1, const float* __restrict__ WhhB1,
    const float* __restrict__ bihB1, const float* __restrict__ bhhB1,
    const float* __restrict__ slope, float* __restrict__ out)
{
    extern __shared__ __align__(128) char smem[];
    const int bx = blockIdx.x;
    if (bx < 128) {
        const int b = bx & 63, dir = bx >> 6;
        if (dir == 0)
            scan_role(smem, b, 0, WhhF0, bhhF0, WihF1, WhhF1, bihF1, bhhF1);
        else
            scan_role(smem, b, 1, WhhB0, bhhB0, WihB1, WhhB1, bihB1, bhhB1);
    } else if (bx < 728) {
        kan_tile<80, 0>(smem, bx - 128, 0, g_hcat, g_W1h, g_W1l, g_y1, slope);
    } else {
        const int z = bx - 728;
        const int cid = z / 3, ny = z % 3;
        kan_tile<88, 2>(smem, cid, ny, g_y1,
                        g_W2h + (size_t)ny * 88 * KF_PAD,
                        g_W2l + (size_t)ny * 88 * KF_PAD, out, slope);
    }
}

// ---------------- launch ----------------
extern "C" void kernel_launch(void* const* d_in, const int* in_sizes, int n_in,
                              void* d_out, int out_size)
{
    const float* x     = (const float*)d_in[0];
    const float* f0Wih = (const float*)d_in[2];
    const float* f0Whh = (const float*)d_in[3];
    const float* f0bih = (const float*)d_in[4];
    const float* f0bhh = (const float*)d_in[5];
    const float* f1Wih = (const float*)d_in[6];
    const float* f1Whh = (const float*)d_in[7];
    const float* f1bih = (const float*)d_in[8];
    const float* f1bhh = (const float*)d_in[9];
    const float* b0Wih = (const float*)d_in[10];
    const float* b0Whh = (const float*)d_in[11];
    const float* b0bih = (const float*)d_in[12];
    const float* b0bhh = (const float*)d_in[13];
    const float* b1Wih = (const float*)d_in[14];
    const float* b1Whh = (const float*)d_in[15];
    const float* b1bih = (const float*)d_in[16];
    const float* b1bhh = (const float*)d_in[17];
    const float* k1b   = (const float*)d_in[18];
    const float* k1s   = (const float*)d_in[19];
    const float* k1c   = (const float*)d_in[20];
    const float* k2b   = (const float*)d_in[21];
    const float* k2s   = (const float*)d_in[22];
    const float* k2c   = (const float*)d_in[23];
    const float* slope = (const float*)d_in[24];
    float* out = (float*)d_out;

    __nv_bfloat16 *p_xhi, *p_xlo;
    cudaGetSymbolAddress((void**)&p_xhi, g_xhi);
    cudaGetSymbolAddress((void**)&p_xlo, g_xlo);

    cudaFuncSetAttribute(hgemm_gates, cudaFuncAttributeMaxDynamicSharedMemorySize, TGg::TOTAL);
    cudaFuncSetAttribute(fused_all,   cudaFuncAttributeMaxDynamicSharedMemorySize, SMEM_FUSED);

    // 1. conversions (+ reset sync counters/flags for this launch)
    conv_x<<<(NTOK * KX_PAD + 255) / 256, 256>>>(x);
    {
        int total = 2 * G3H * KX_PAD + TWOH * KF_PAD + 264 * KF_PAD;
        pack_weights<<<(total + 255) / 256, 256>>>(f0Wih, b0Wih, k1b, k1s, k1c, k2b, k2s, k2c);
    }
    // 2. layer-0 input gates (both directions)
    {
        dim3 grid(NTOK / 64, 2);
        hgemm_gates<<<grid, 128, TGg::TOTAL>>>(p_xhi, p_xlo, f0bih, b0bih);
    }
    // 3. fused: GRU scan + gated kan1 + gated kan2 (overlapped)
    {
        fused_all<<<128 + 600 + 1800, 160, SMEM_FUSED>>>(
            f0Whh, f0bhh, f1Wih, f1Whh, f1bih, f1bhh,
            b0Whh, b0bhh, b1Wih, b1Whh, b1bih, b1bhh,
            slope, out);
    }
    (void)in_sizes; (void)n_in; (void)out_size;
}

// round 14
// speedup vs baseline: 1.1004x; 1.1004x over previous
#include <cuda_runtime.h>
#include <cuda_bf16.h>
#include <math.h>
#include <stdint.h>

// ---------------- problem constants ----------------
#define T_STEPS 600
#define BATCH   64
#define HID     40
#define IN_F    257
#define NTOK    (BATCH * T_STEPS)   // 38400
#define G3H     120                 // 3*HID
#define TWOH    80
#define KX_PAD  320
#define KF_PAD  768

// ---------------- scratch ----------------
__device__ float g_giF[(size_t)T_STEPS * BATCH * G3H];
__device__ float g_giB[(size_t)T_STEPS * BATCH * G3H];
__device__ float g_hcat[(size_t)NTOK * TWOH];
__device__ float g_y1[(size_t)NTOK * TWOH];
__device__ __nv_bfloat16 g_xhi[(size_t)NTOK * KX_PAD];
__device__ __nv_bfloat16 g_xlo[(size_t)NTOK * KX_PAD];
__device__ __nv_bfloat16 g_Wgh[2 * G3H * KX_PAD];
__device__ __nv_bfloat16 g_Wgl[2 * G3H * KX_PAD];
__device__ __nv_bfloat16 g_W1h[TWOH * KF_PAD];
__device__ __nv_bfloat16 g_W1l[TWOH * KF_PAD];
__device__ __nv_bfloat16 g_W2h[264 * KF_PAD];
__device__ __nv_bfloat16 g_W2l[264 * KF_PAD];

#define SMEM_SWIZZLE_128B(x) ((x) ^ (((x) >> 3) & 0x70))

__device__ __forceinline__ uint32_t smem_to_u32(const void* p) {
    uint32_t a;
    asm("{ .reg .u64 t; cvta.to.shared.u64 t, %1; cvt.u32.u64 %0, t; }" : "=r"(a) : "l"(p));
    return a;
}

// ---------------- warp MMA helpers ----------------
__device__ __forceinline__ void ldsm_x4(uint32_t* r, uint32_t addr) {
    asm volatile("ldmatrix.sync.aligned.m8n8.x4.shared.b16 {%0,%1,%2,%3}, [%4];"
                 : "=r"(r[0]), "=r"(r[1]), "=r"(r[2]), "=r"(r[3]) : "r"(addr));
}
__device__ __forceinline__ void ldsm_x2(uint32_t* r, uint32_t addr) {
    asm volatile("ldmatrix.sync.aligned.m8n8.x2.shared.b16 {%0,%1}, [%2];"
                 : "=r"(r[0]), "=r"(r[1]) : "r"(addr));
}
__device__ __forceinline__ void mma_bf16(float* c, const uint32_t* a, const uint32_t* b) {
    asm volatile("mma.sync.aligned.m16n8k16.row.col.f32.bf16.bf16.f32 "
                 "{%0,%1,%2,%3}, {%4,%5,%6,%7}, {%8,%9}, {%0,%1,%2,%3};"
                 : "+f"(c[0]), "+f"(c[1]), "+f"(c[2]), "+f"(c[3])
                 : "r"(a[0]), "r"(a[1]), "r"(a[2]), "r"(a[3]), "r"(b[0]), "r"(b[1]));
}
__device__ __forceinline__ void cp16(uint32_t saddr, const void* g) {
    asm volatile("cp.async.cg.shared.global [%0], [%1], 16;" :: "r"(saddr), "l"(g));
}
#define CP_COMMIT() asm volatile("cp.async.commit_group;" ::: "memory")
#define CP_WAIT1()  asm volatile("cp.async.wait_group 1;" ::: "memory")

__device__ __forceinline__ void split_bf16(float v, __nv_bfloat16& h, __nv_bfloat16& l) {
    h = __float2bfloat16(v);
    l = __float2bfloat16(v - __bfloat162float(h));
}

__device__ __forceinline__ float gridv(int j) { return 0.4f * (float)(j - 3) - 1.0f; }

__device__ __forceinline__ void basis8(float x, float* o) {
    float bset[11];
#pragma unroll
    for (int j = 0; j < 11; j++)
        bset[j] = (x >= gridv(j) && x < gridv(j + 1)) ? 1.0f : 0.0f;
#pragma unroll
    for (int j = 0; j < 10; j++)
        bset[j] = (x - gridv(j)) * 2.5f * bset[j] + (gridv(j + 2) - x) * 2.5f * bset[j + 1];
#pragma unroll
    for (int j = 0; j < 9; j++)
        bset[j] = (x - gridv(j)) * 1.25f * bset[j] + (gridv(j + 3) - x) * 1.25f * bset[j + 1];
#pragma unroll
    for (int j = 0; j < 8; j++)
        o[j] = (x - gridv(j)) * (1.0f / 1.2f) * bset[j] + (gridv(j + 4) - x) * (1.0f / 1.2f) * bset[j + 1];
}

// ---------------- conversion kernels ----------------
__global__ void conv_x(const float* __restrict__ x) {
    int idx = blockIdx.x * blockDim.x + threadIdx.x;
    if (idx >= NTOK * KX_PAD) return;
    int row = idx / KX_PAD, col = idx % KX_PAD;
    float v = (col < IN_F) ? x[(size_t)row * IN_F + col] : 0.0f;
    __nv_bfloat16 h, l; split_bf16(v, h, l);
    g_xhi[idx] = h; g_xlo[idx] = l;
}

__global__ void pack_weights(const float* __restrict__ f0W, const float* __restrict__ b0W,
                             const float* __restrict__ k1b, const float* __restrict__ k1s,
                             const float* __restrict__ k1c,
                             const float* __restrict__ k2b, const float* __restrict__ k2s,
                             const float* __restrict__ k2c)
{
    const int NG = 2 * G3H * KX_PAD;
    const int N1 = TWOH * KF_PAD;
    const int N2 = 264 * KF_PAD;
    int idx = blockIdx.x * blockDim.x + threadIdx.x;
    if (idx >= NG + N1 + N2) return;
    float v = 0.0f;
    if (idx < NG) {
        int d = idx / (G3H * KX_PAD), r = (idx / KX_PAD) % G3H, c = idx % KX_PAD;
        if (c < IN_F) v = d ? b0W[r * IN_F + c] : f0W[r * IN_F + c];
        __nv_bfloat16 h, l; split_bf16(v, h, l);
        g_Wgh[idx] = h; g_Wgl[idx] = l;
        return;
    }
    idx -= NG;
    if (idx < N1) {
        int o = idx / KF_PAD, k = idx % KF_PAD;
        if (k < TWOH) v = k1b[o * TWOH + k];
        else if (k < 720) {
            int e = k - TWOH, i = e >> 3, g = e & 7;
            v = k1s[(o * TWOH + i) * 8 + g] * k1c[o * TWOH + i];
        }
        __nv_bfloat16 h, l; split_bf16(v, h, l);
        g_W1h[idx] = h; g_W1l[idx] = l;
        return;
    }
    idx -= N1;
    {
        int o = idx / KF_PAD, k = idx % KF_PAD;
        if (o < IN_F) {
            if (k < TWOH) v = k2b[o * TWOH + k];
            else if (k < 720) {
                int e = k - TWOH, i = e >> 3, g = e & 7;
                v = k2s[(o * TWOH + i) * 8 + g] * k2c[o * TWOH + i];
            }
        }
        __nv_bfloat16 h, l; split_bf16(v, h, l);
        g_W2h[idx] = h; g_W2l[idx] = l;
    }
}

// ---------------- gates GEMM (M64, 128 threads, cp.async 2-stage) ----------------
struct TGg {
    static constexpr int N128    = 120 * 128;
    static constexpr int OFF_AHI = 0;
    static constexpr int OFF_ALO = 8192;
    static constexpr int OFF_BHI = 16384;
    static constexpr int OFF_BLO = 16384 + N128;
    static constexpr int STAGE   = 16384 + 2 * N128;
    static constexpr int TOTAL   = 2 * STAGE;
};

__global__ __launch_bounds__(128) void hgemm_gates(
    const __nv_bfloat16* __restrict__ Ahi, const __nv_bfloat16* __restrict__ Alo,
    const float* __restrict__ biasF, const float* __restrict__ biasB)
{
    constexpr int NT8 = 15;
    extern __shared__ __align__(128) char smem[];
    const uint32_t smemB = smem_to_u32(smem);
    const int tid = threadIdx.x, wid = tid >> 5, lid = tid & 31;

    const __nv_bfloat16* Bhi = g_Wgh + (size_t)blockIdx.y * G3H * KX_PAD;
    const __nv_bfloat16* Blo = g_Wgl + (size_t)blockIdx.y * G3H * KX_PAD;
    const size_t aRow0 = (size_t)blockIdx.x * 64;

    float acc[NT8][4];
#pragma unroll
    for (int t = 0; t < NT8; t++)
#pragma unroll
        for (int j = 0; j < 4; j++) acc[t][j] = 0.0f;

    const int rwA = wid * 16 + (lid & 15);
    const int khA = lid >> 4;
    const int bTs = (lid >> 4) & 1, bKh = (lid >> 3) & 1, bRow = lid & 7;

    auto load_chunk = [&](int kc, int st) {
        const int kOff = kc << 6;
        const uint32_t base = smemB + st * TGg::STAGE;
#pragma unroll
        for (int j = 0; j < 4; j++) {
            int s = j * 128 + tid;
            int r = s >> 3, c = s & 7;
            size_t go = (aRow0 + r) * (size_t)KX_PAD + kOff + c * 8;
            uint32_t sw = SMEM_SWIZZLE_128B((uint32_t)(r * 128 + c * 16));
            cp16(base + TGg::OFF_AHI + sw, Ahi + go);
            cp16(base + TGg::OFF_ALO + sw, Alo + go);
        }
        for (int s = tid; s < 120 * 8; s += 128) {
            int r = s >> 3, c = s & 7;
            size_t go = (size_t)r * KX_PAD + kOff + c * 8;
            uint32_t sw = SMEM_SWIZZLE_128B((uint32_t)(r * 128 + c * 16));
            cp16(base + TGg::OFF_BHI + sw, Bhi + go);
            cp16(base + TGg::OFF_BLO + sw, Blo + go);
        }
    };

    const int nchunk = KX_PAD >> 6;
    load_chunk(0, 0);
    CP_COMMIT();
    for (int kc = 0; kc < nchunk; kc++) {
        if (kc + 1 < nchunk) load_chunk(kc + 1, (kc + 1) & 1);
        CP_COMMIT();
        CP_WAIT1();
        __syncthreads();
        const uint32_t base = smemB + (kc & 1) * TGg::STAGE;
#pragma unroll
        for (int ks = 0; ks < 4; ks++) {
            uint32_t ah[4], al[4];
            uint32_t offA = SMEM_SWIZZLE_128B((uint32_t)(rwA * 128 + ks * 32 + khA * 16));
            ldsm_x4(ah, base + TGg::OFF_AHI + offA);
            ldsm_x4(al, base + TGg::OFF_ALO + offA);
#pragma unroll
            for (int nt = 0; nt < NT8; nt += 2) {
                uint32_t bh[4], bl[4];
                if (nt + 1 < NT8) {
                    int n = (nt + bTs) * 8 + bRow;
                    uint32_t off = SMEM_SWIZZLE_128B((uint32_t)(n * 128 + ks * 32 + bKh * 16));
                    ldsm_x4(bh, base + TGg::OFF_BHI + off);
                    ldsm_x4(bl, base + TGg::OFF_BLO + off);
                } else {
                    int n = nt * 8 + bRow;
                    uint32_t off = SMEM_SWIZZLE_128B((uint32_t)(n * 128 + ks * 32 + bKh * 16));
                    ldsm_x2(bh, base + TGg::OFF_BHI + off);
                    ldsm_x2(bl, base + TGg::OFF_BLO + off);
                }
                mma_bf16(acc[nt], ah, bh);
                mma_bf16(acc[nt], al, bh);
                mma_bf16(acc[nt], ah, bl);
                if (nt + 1 < NT8) {
                    mma_bf16(acc[nt + 1], ah, bh + 2);
                    mma_bf16(acc[nt + 1], al, bh + 2);
                    mma_bf16(acc[nt + 1], ah, bl + 2);
                }
            }
        }
        __syncthreads();
    }

    const int r0 = (int)aRow0 + wid * 16 + (lid >> 2);
    const int cO = 2 * (lid & 3);
    float* baseO = blockIdx.y ? g_giB : g_giF;
    const float* bia = blockIdx.y ? biasB : biasF;
    int b0 = r0 / T_STEPS, t0 = r0 % T_STEPS;
    int b1 = (r0 + 8) / T_STEPS, t1 = (r0 + 8) % T_STEPS;
    float* d0 = baseO + ((size_t)t0 * BATCH + b0) * G3H;
    float* d1 = baseO + ((size_t)t1 * BATCH + b1) * G3H;
#pragma unroll
    for (int t = 0; t < NT8; t++) {
        int cb = t * 8 + cO;
        d0[cb]     = acc[t][0] + bia[cb];
        d0[cb + 1] = acc[t][1] + bia[cb + 1];
        d1[cb]     = acc[t][2] + bia[cb];
        d1[cb + 1] = acc[t][3] + bia[cb + 1];
    }
}

// ---------------- GRU helpers ----------------
__device__ __forceinline__ float sigm_fast(float x) {
    float e = __expf(-x);
    return __fdividef(1.0f, 1.0f + e);
}
__device__ __forceinline__ float tanh_fast(float x) {
    float e = __expf(2.0f * x);
    return 1.0f - __fdividef(2.0f, 1.0f + e);
}

// ---------------- GRU scan (R7 version: 320 threads, 1 barrier/step) ----------------
__global__ __launch_bounds__(320) void gru_scan2(
    const float* __restrict__ WhhF0, const float* __restrict__ bhhF0,
    const float* __restrict__ WihF1, const float* __restrict__ WhhF1,
    const float* __restrict__ bihF1, const float* __restrict__ bhhF1,
    const float* __restrict__ WhhB0, const float* __restrict__ bhhB0,
    const float* __restrict__ WihB1, const float* __restrict__ WhhB1,
    const float* __restrict__ bihB1, const float* __restrict__ bhhB1)
{
    const int b   = blockIdx.x;
    const int dir = blockIdx.y;
    const float* Whh0 = dir ? WhhB0 : WhhF0;
    const float* bhh0 = dir ? bhhB0 : bhhF0;
    const float* W1ih = dir ? WihB1 : WihF1;
    const float* W1hh = dir ? WhhB1 : WhhF1;
    const float* b1ih = dir ? bihB1 : bihF1;
    const float* b1hh = dir ? bhhB1 : bhhF1;
    const float* gi   = dir ? g_giB : g_giF;
    float* out = g_hcat + (size_t)b * T_STEPS * TWOH + dir * HID;

    __shared__ float s_h0[2][HID];
    __shared__ float s_h1[2][HID];

    const int tid = threadIdx.x;
    const bool isA = tid < 160;
    const int lane = isA ? tid : tid - 160;
    const int unit = lane >> 2;
    const int q    = lane & 3;
    const int k0   = q * 10;

    float wA[3][10];
    float wI[3][10], wH[3][10];
    float brz0 = 0.f, brz1 = 0.f, bn0 = 0.f;
    float bR = 0.f, bZ = 0.f, bIN = 0.f, bHN = 0.f;
    if (isA) {
#pragma unroll
        for (int g = 0; g < 3; g++)
#pragma unroll
            for (int k = 0; k < 10; k++)
                wA[g][k] = Whh0[(g * HID + unit) * HID + k0 + k];
        brz0 = bhh0[unit];
        brz1 = bhh0[HID + unit];
        bn0  = bhh0[2 * HID + unit];
    } else {
#pragma unroll
        for (int g = 0; g < 3; g++)
#pragma unroll
            for (int k = 0; k < 10; k++) {
                wI[g][k] = W1ih[(g * HID + unit) * HID + k0 + k];
                wH[g][k] = W1hh[(g * HID + unit) * HID + k0 + k];
            }
        bR  = b1ih[unit]           + b1hh[unit];
        bZ  = b1ih[HID + unit]     + b1hh[HID + unit];
        bIN = b1ih[2 * HID + unit];
        bHN = b1hh[2 * HID + unit];
    }

    if (tid < HID) { s_h0[0][tid] = 0.0f; s_h0[1][tid] = 0.0f;
                     s_h1[0][tid] = 0.0f; s_h1[1][tid] = 0.0f; }

    float gc0 = 0.f, gc1 = 0.f, gc2 = 0.f;
    if (isA) {
        int grow = dir ? (T_STEPS - 1) : 0;
        const float* gp = gi + ((size_t)grow * BATCH + b) * G3H;
        gc0 = gp[unit]; gc1 = gp[HID + unit]; gc2 = gp[2 * HID + unit];
    }
    __syncthreads();

    for (int s = 0; s <= T_STEPS; s++) {
        const int cur = s & 1, nxt = (s & 1) ^ 1;
        float gn0 = 0.f, gn1 = 0.f, gn2 = 0.f;

        if (isA) {
            if (s + 1 < T_STEPS) {
                int grow = dir ? (T_STEPS - 2 - s) : (s + 1);
                const float* gp = gi + ((size_t)grow * BATCH + b) * G3H;
                gn0 = gp[unit]; gn1 = gp[HID + unit]; gn2 = gp[2 * HID + unit];
            }
            if (s < T_STEPS) {
                const float* h0c = s_h0[cur];
                float hk[10];
                {
                    const float2* h2 = (const float2*)(h0c + k0);
#pragma unroll
                    for (int k = 0; k < 5; k++) {
                        float2 v = h2[k];
                        hk[2 * k] = v.x; hk[2 * k + 1] = v.y;
                    }
                }
                float p0 = 0.f, p1 = 0.f, p2 = 0.f;
#pragma unroll
                for (int k = 0; k < 10; k++) {
                    p0 = fmaf(wA[0][k], hk[k], p0);
                    p1 = fmaf(wA[1][k], hk[k], p1);
                    p2 = fmaf(wA[2][k], hk[k], p2);
                }
                p0 += __shfl_xor_sync(0xffffffffu, p0, 1);
                p0 += __shfl_xor_sync(0xffffffffu, p0, 2);
                p1 += __shfl_xor_sync(0xffffffffu, p1, 1);
                p1 += __shfl_xor_sync(0xffffffffu, p1, 2);
                p2 += __shfl_xor_sync(0xffffffffu, p2, 1);
                p2 += __shfl_xor_sync(0xffffffffu, p2, 2);
                float r = sigm_fast(gc0 + p0 + brz0);
                float z = sigm_fast(gc1 + p1 + brz1);
                float n = tanh_fast(gc2 + r * (p2 + bn0));
                float hnew = (1.0f - z) * n + z * h0c[unit];
                if (q == 0) s_h0[nxt][unit] = hnew;
            }
        } else {
            if (s >= 1) {
                const float* h0c = s_h0[cur];
                const float* h1c = s_h1[cur];
                float a[10], hh[10];
                {
                    const float2* a2 = (const float2*)(h0c + k0);
                    const float2* b2 = (const float2*)(h1c + k0);
#pragma unroll
                    for (int k = 0; k < 5; k++) {
                        float2 va = a2[k], vb = b2[k];
                        a[2 * k] = va.x; a[2 * k + 1] = va.y;
                        hh[2 * k] = vb.x; hh[2 * k + 1] = vb.y;
                    }
                }
                float pr = 0.f, pz = 0.f, pin = 0.f, phn = 0.f;
#pragma unroll
                for (int k = 0; k < 10; k++) {
                    pr  = fmaf(wI[0][k], a[k], pr);
                    pz  = fmaf(wI[1][k], a[k], pz);
                    pin = fmaf(wI[2][k], a[k], pin);
                    phn = fmaf(wH[2][k], hh[k], phn);
                }
#pragma unroll
                for (int k = 0; k < 10; k++) {
                    pr = fmaf(wH[0][k], hh[k], pr);
                    pz = fmaf(wH[1][k], hh[k], pz);
                }
                pr  += __shfl_xor_sync(0xffffffffu, pr, 1);
                pr  += __shfl_xor_sync(0xffffffffu, pr, 2);
                pz  += __shfl_xor_sync(0xffffffffu, pz, 1);
                pz  += __shfl_xor_sync(0xffffffffu, pz, 2);
                pin += __shfl_xor_sync(0xffffffffu, pin, 1);
                pin += __shfl_xor_sync(0xffffffffu, pin, 2);
                phn += __shfl_xor_sync(0xffffffffu, phn, 1);
                phn += __shfl_xor_sync(0xffffffffu, phn, 2);
                float r = sigm_fast(pr + bR);
                float z = sigm_fast(pz + bZ);
                float n = tanh_fast(pin + bIN + r * (phn + bHN));
                float h = (1.0f - z) * n + z * h1c[unit];
                if (q == 0) {
                    s_h1[nxt][unit] = h;
                    out[(size_t)(s - 1) * TWOH + unit] = h;
                }
            }
        }
        __syncthreads();
        gc0 = gn0; gc1 = gn1; gc2 = gn2;
    }
}

// ---------------- fused KAN kernel (expansion in-kernel, validated in R13) ----------------
#define OFF_X    0
#define OFF_AHI_ 20480
#define OFF_ALO_ 28672
#define OFF_B_   36864

template <int N_TILE>
struct TK {
    static constexpr int B_HALF  = N_TILE * 128;
    static constexpr int B_STAGE = 2 * B_HALF;
    static constexpr int TOTAL   = OFF_B_ + 2 * B_STAGE;
};

template <int N_TILE, int EPI>
__global__ __launch_bounds__(128) void kan_fused(
    const float* __restrict__ Xsrc,
    const __nv_bfloat16* __restrict__ BhiAll, const __nv_bfloat16* __restrict__ BloAll,
    float* __restrict__ outP, const float* __restrict__ slope)
{
    constexpr int NT8 = N_TILE / 8;
    extern __shared__ __align__(128) char smem[];
    const uint32_t smemB = smem_to_u32(smem);
    const int tid = threadIdx.x;
    const int r0 = blockIdx.x * 64;
    const int ny = blockIdx.y;
    float* sX = (float*)(smem + OFF_X);

    const __nv_bfloat16* Bhi = BhiAll + (size_t)ny * N_TILE * KF_PAD;
    const __nv_bfloat16* Blo = BloAll + (size_t)ny * N_TILE * KF_PAD;

    // load X tile (64 x 80 fp32)
    {
        const float4* src = (const float4*)(Xsrc + (size_t)r0 * TWOH);
        float4* dst = (float4*)sX;
        for (int i = tid; i < 64 * TWOH / 4; i += 128) dst[i] = src[i];
    }
    __syncthreads();

    float acc[NT8][4];
#pragma unroll
    for (int t = 0; t < NT8; t++)
#pragma unroll
        for (int j = 0; j < 4; j++) acc[t][j] = 0.0f;

    const int wid = tid >> 5, lid = tid & 31;
    const int rwA = wid * 16 + (lid & 15);
    const int khA = lid >> 4;
    const int bTs = (lid >> 4) & 1, bKh = (lid >> 3) & 1, bRow = lid & 7;

    auto loadB = [&](int kc, int st) {
        const int kOff = kc << 6;
        uint32_t bHiB = smemB + OFF_B_ + st * TK<N_TILE>::B_STAGE;
        for (int s = tid; s < N_TILE * 8; s += 128) {
            int r = s >> 3, c = s & 7;
            size_t go = (size_t)r * KF_PAD + kOff + c * 8;
            uint32_t sw = SMEM_SWIZZLE_128B((uint32_t)(r * 128 + c * 16));
            cp16(bHiB + sw, Bhi + go);
            cp16(bHiB + TK<N_TILE>::B_HALF + sw, Blo + go);
        }
    };

    loadB(0, 0);
    CP_COMMIT();

    for (int kc = 0; kc < 12; kc++) {
        if (kc + 1 < 12) loadB(kc + 1, (kc + 1) & 1);
        CP_COMMIT();
        // expand A chunk into smem (64 rows x 64 bf16 hi/lo)
        {
            const int kOff = kc << 6;
#pragma unroll
            for (int j = 0; j < 4; j++) {
                int g = j * 128 + tid;
                int row = g >> 3, cg = g & 7;
                int c0 = kOff + cg * 8;
                union { __nv_bfloat16 b[8]; uint4 u; } hv, lv;
                if (c0 < TWOH) {
#pragma unroll
                    for (int k2 = 0; k2 < 8; k2++) {
                        float xv = sX[row * TWOH + c0 + k2];
                        float sv = xv * __fdividef(1.0f, 1.0f + __expf(-xv));
                        split_bf16(sv, hv.b[k2], lv.b[k2]);
                    }
                } else {
                    int u = (c0 - TWOH) >> 3;
                    if (u < TWOH) {
                        float xv = sX[row * TWOH + u];
                        float bs[8];
                        basis8(xv, bs);
#pragma unroll
                        for (int k2 = 0; k2 < 8; k2++) split_bf16(bs[k2], hv.b[k2], lv.b[k2]);
                    } else {
                        hv.u = make_uint4(0, 0, 0, 0);
                        lv.u = make_uint4(0, 0, 0, 0);
                    }
                }
                uint32_t sw = SMEM_SWIZZLE_128B((uint32_t)(row * 128 + cg * 16));
                *(uint4*)(smem + OFF_AHI_ + sw) = hv.u;
                *(uint4*)(smem + OFF_ALO_ + sw) = lv.u;
            }
        }
        CP_WAIT1();
        __syncthreads();

        {
            const uint32_t bHiB = smemB + OFF_B_ + (kc & 1) * TK<N_TILE>::B_STAGE;
            const uint32_t bLoB = bHiB + TK<N_TILE>::B_HALF;
            const uint32_t aHiB = smemB + OFF_AHI_;
            const uint32_t aLoB = smemB + OFF_ALO_;
#pragma unroll
            for (int ks = 0; ks < 4; ks++) {
                uint32_t ah[4], al[4];
                uint32_t offA = SMEM_SWIZZLE_128B((uint32_t)(rwA * 128 + ks * 32 + khA * 16));
                ldsm_x4(ah, aHiB + offA);
                ldsm_x4(al, aLoB + offA);
#pragma unroll
                for (int nt = 0; nt < NT8; nt += 2) {
                    uint32_t bh[4], bl[4];
                    if (nt + 1 < NT8) {
                        int n = (nt + bTs) * 8 + bRow;
                        uint32_t off = SMEM_SWIZZLE_128B((uint32_t)(n * 128 + ks * 32 + bKh * 16));
                        ldsm_x4(bh, bHiB + off);
                        ldsm_x4(bl, bLoB + off);
                    } else {
                        int n = nt * 8 + bRow;
                        uint32_t off = SMEM_SWIZZLE_128B((uint32_t)(n * 128 + ks * 32 + bKh * 16));
                        ldsm_x2(bh, bHiB + off);
                        ldsm_x2(bl, bLoB + off);
                    }
                    mma_bf16(acc[nt], ah, bh);
                    mma_bf16(acc[nt], al, bh);
                    mma_bf16(acc[nt], ah, bl);
                    if (nt + 1 < NT8) {
                        mma_bf16(acc[nt + 1], ah, bh + 2);
                        mma_bf16(acc[nt + 1], al, bh + 2);
                        mma_bf16(acc[nt + 1], ah, bl + 2);
                    }
                }
            }
        }
        __syncthreads();
    }

    // epilogue
    const int rr = r0 + wid * 16 + (lid >> 2);
    const int cO = 2 * (lid & 3);
    if (EPI == 0) {
#pragma unroll
        for (int t = 0; t < NT8; t++) {
            int cb = t * 8 + cO;
            float* o0 = outP + (size_t)rr * TWOH + cb;
            float* o1 = outP + (size_t)(rr + 8) * TWOH + cb;
            o0[0] = acc[t][0]; o0[1] = acc[t][1];
            o1[0] = acc[t][2]; o1[1] = acc[t][3];
        }
    } else {
        const int cbase = ny * 88;
#pragma unroll
        for (int t = 0; t < NT8; t++) {
            int cb = cbase + t * 8 + cO;
#pragma unroll
            for (int j = 0; j < 2; j++) {
                int cg = cb + j;
                if (cg < IN_F) {
                    outP[(size_t)rr * IN_F + cg] =
                        1.2f / (1.0f + expf(-slope[cg] * acc[t][j]));
                    outP[(size_t)(rr + 8) * IN_F + cg] =
                        1.2f / (1.0f + expf(-slope[cg] * acc[t][2 + j]));
                }
            }
        }
    }
}

// ---------------- launch ----------------
extern "C" void kernel_launch(void* const* d_in, const int* in_sizes, int n_in,
                              void* d_out, int out_size)
{
    const float* x     = (const float*)d_in[0];
    const float* f0Wih = (const float*)d_in[2];
    const float* f0Whh = (const float*)d_in[3];
    const float* f0bih = (const float*)d_in[4];
    const float* f0bhh = (const float*)d_in[5];
    const float* f1Wih = (const float*)d_in[6];
    const float* f1Whh = (const float*)d_in[7];
    const float* f1bih = (const float*)d_in[8];
    const float* f1bhh = (const float*)d_in[9];
    const float* b0Wih = (const float*)d_in[10];
    const float* b0Whh = (const float*)d_in[11];
    const float* b0bih = (const float*)d_in[12];
    const float* b0bhh = (const float*)d_in[13];
    const float* b1Wih = (const float*)d_in[14];
    const float* b1Whh = (const float*)d_in[15];
    const float* b1bih = (const float*)d_in[16];
    const float* b1bhh = (const float*)d_in[17];
    const float* slope = (const float*)d_in[24];
    float* out = (float*)d_out;

    __nv_bfloat16 *p_xhi, *p_xlo, *p_W1h, *p_W1l, *p_W2h, *p_W2l;
    float *p_hcat, *p_y1;
    cudaGetSymbolAddress((void**)&p_xhi, g_xhi);
    cudaGetSymbolAddress((void**)&p_xlo, g_xlo);
    cudaGetSymbolAddress((void**)&p_W1h, g_W1h);
    cudaGetSymbolAddress((void**)&p_W1l, g_W1l);
    cudaGetSymbolAddress((void**)&p_W2h, g_W2h);
    cudaGetSymbolAddress((void**)&p_W2l, g_W2l);
    cudaGetSymbolAddress((void**)&p_hcat, g_hcat);
    cudaGetSymbolAddress((void**)&p_y1, g_y1);

    cudaFuncSetAttribute(hgemm_gates, cudaFuncAttributeMaxDynamicSharedMemorySize, TGg::TOTAL);
    cudaFuncSetAttribute(kan_fused<80, 0>, cudaFuncAttributeMaxDynamicSharedMemorySize, TK<80>::TOTAL);
    cudaFuncSetAttribute(kan_fused<88, 2>, cudaFuncAttributeMaxDynamicSharedMemorySize, TK<88>::TOTAL);

    // 1. conversions
    conv_x<<<(NTOK * KX_PAD + 255) / 256, 256>>>(x);
    {
        const float* k1b = (const float*)d_in[18];
        const float* k1s = (const float*)d_in[19];
        const float* k1c = (const float*)d_in[20];
        const float* k2b = (const float*)d_in[21];
        const float* k2s = (const float*)d_in[22];
        const float* k2c = (const float*)d_in[23];
        int total = 2 * G3H * KX_PAD + TWOH * KF_PAD + 264 * KF_PAD;
        pack_weights<<<(total + 255) / 256, 256>>>(f0Wih, b0Wih, k1b, k1s, k1c, k2b, k2s, k2c);
    }
    // 2. layer-0 input gates
    {
        dim3 grid(NTOK / 64, 2);
        hgemm_gates<<<grid, 128, TGg::TOTAL>>>(p_xhi, p_xlo, f0bih, b0bih);
    }
    // 3. GRU scan (R7 version — measured best)
    {
        dim3 grid(BATCH, 2);
        gru_scan2<<<grid, 320>>>(f0Whh, f0bhh, f1Wih, f1Whh, f1bih, f1bhh,
                                 b0Whh, b0bhh, b1Wih, b1Whh, b1bih, b1bhh);
    }
    // 4. KAN layer 1 (fused expansion + HMMA)
    {
        dim3 grid(NTOK / 64, 1);
        kan_fused<80, 0><<<grid, 128, TK<80>::TOTAL>>>(p_hcat, p_W1h, p_W1l, p_y1, slope);
    }
    // 5. KAN layer 2 (fused expansion + HMMA + sigmoid)
    {
        dim3 grid(NTOK / 64, 3);
        kan_fused<88, 2><<<grid, 128, TK<88>::TOTAL>>>(p_y1, p_W2h, p_W2l, out, slope);
    }
    (void)in_sizes; (void)n_in; (void)out_size;
}

// round 15
// speedup vs baseline: 1.3333x; 1.2116x over previous
#include <cuda_runtime.h>
#include <cuda_bf16.h>
#include <math.h>
#include <stdint.h>

// ---------------- problem constants ----------------
#define T_STEPS 600
#define BATCH   64
#define HID     40
#define IN_F    257
#define NTOK    (BATCH * T_STEPS)   // 38400
#define G3H     120
#define TWOH    80
#define KX_PAD  320
#define KF_PAD  768

// ---------------- scratch ----------------
__device__ float g_giF[(size_t)T_STEPS * BATCH * G3H];
__device__ float g_giB[(size_t)T_STEPS * BATCH * G3H];
__device__ float g_hcat[(size_t)NTOK * TWOH];
__device__ float g_y1[(size_t)NTOK * TWOH];
__device__ __nv_bfloat16 g_xhi[(size_t)NTOK * KX_PAD];
__device__ __nv_bfloat16 g_xlo[(size_t)NTOK * KX_PAD];
__device__ __nv_bfloat16 g_fhi[(size_t)NTOK * KF_PAD];
__device__ __nv_bfloat16 g_flo[(size_t)NTOK * KF_PAD];
__device__ __nv_bfloat16 g_Wgh[2 * G3H * KX_PAD];
__device__ __nv_bfloat16 g_Wgl[2 * G3H * KX_PAD];
__device__ __nv_bfloat16 g_W1h[TWOH * KF_PAD];
__device__ __nv_bfloat16 g_W1l[TWOH * KF_PAD];
__device__ __nv_bfloat16 g_W2h[264 * KF_PAD];
__device__ __nv_bfloat16 g_W2l[264 * KF_PAD];

#define SMEM_SWIZZLE_128B(x) ((x) ^ (((x) >> 3) & 0x70))

__device__ __forceinline__ uint32_t smem_to_u32(const void* p) {
    uint32_t a;
    asm("{ .reg .u64 t; cvta.to.shared.u64 t, %1; cvt.u32.u64 %0, t; }" : "=r"(a) : "l"(p));
    return a;
}

// ---------------- warp MMA helpers ----------------
__device__ __forceinline__ void ldsm_x4(uint32_t* r, uint32_t addr) {
    asm volatile("ldmatrix.sync.aligned.m8n8.x4.shared.b16 {%0,%1,%2,%3}, [%4];"
                 : "=r"(r[0]), "=r"(r[1]), "=r"(r[2]), "=r"(r[3]) : "r"(addr));
}
__device__ __forceinline__ void ldsm_x2(uint32_t* r, uint32_t addr) {
    asm volatile("ldmatrix.sync.aligned.m8n8.x2.shared.b16 {%0,%1}, [%2];"
                 : "=r"(r[0]), "=r"(r[1]) : "r"(addr));
}
__device__ __forceinline__ void mma_bf16(float* c, const uint32_t* a, const uint32_t* b) {
    asm volatile("mma.sync.aligned.m16n8k16.row.col.f32.bf16.bf16.f32 "
                 "{%0,%1,%2,%3}, {%4,%5,%6,%7}, {%8,%9}, {%0,%1,%2,%3};"
                 : "+f"(c[0]), "+f"(c[1]), "+f"(c[2]), "+f"(c[3])
                 : "r"(a[0]), "r"(a[1]), "r"(a[2]), "r"(a[3]), "r"(b[0]), "r"(b[1]));
}
__device__ __forceinline__ void cp16(uint32_t saddr, const void* g) {
    asm volatile("cp.async.cg.shared.global [%0], [%1], 16;" :: "r"(saddr), "l"(g));
}
#define CP_COMMIT() asm volatile("cp.async.commit_group;" ::: "memory")
#define CP_WAIT1()  asm volatile("cp.async.wait_group 1;" ::: "memory")

__device__ __forceinline__ void split_bf16(float v, __nv_bfloat16& h, __nv_bfloat16& l) {
    h = __float2bfloat16(v);
    l = __float2bfloat16(v - __bfloat162float(h));
}

// ---------------- conversion kernels ----------------
__global__ void conv_x(const float* __restrict__ x) {
    int idx = blockIdx.x * blockDim.x + threadIdx.x;
    if (idx >= NTOK * KX_PAD) return;
    int row = idx / KX_PAD, col = idx % KX_PAD;
    float v = (col < IN_F) ? x[(size_t)row * IN_F + col] : 0.0f;
    __nv_bfloat16 h, l; split_bf16(v, h, l);
    g_xhi[idx] = h; g_xlo[idx] = l;
}

__global__ void pack_weights(const float* __restrict__ f0W, const float* __restrict__ b0W,
                             const float* __restrict__ k1b, const float* __restrict__ k1s,
                             const float* __restrict__ k1c,
                             const float* __restrict__ k2b, const float* __restrict__ k2s,
                             const float* __restrict__ k2c)
{
    const int NG = 2 * G3H * KX_PAD;
    const int N1 = TWOH * KF_PAD;
    const int N2 = 264 * KF_PAD;
    int idx = blockIdx.x * blockDim.x + threadIdx.x;
    if (idx >= NG + N1 + N2) return;
    float v = 0.0f;
    if (idx < NG) {
        int d = idx / (G3H * KX_PAD), r = (idx / KX_PAD) % G3H, c = idx % KX_PAD;
        if (c < IN_F) v = d ? b0W[r * IN_F + c] : f0W[r * IN_F + c];
        __nv_bfloat16 h, l; split_bf16(v, h, l);
        g_Wgh[idx] = h; g_Wgl[idx] = l;
        return;
    }
    idx -= NG;
    if (idx < N1) {
        int o = idx / KF_PAD, k = idx % KF_PAD;
        if (k < TWOH) v = k1b[o * TWOH + k];
        else if (k < 720) {
            int e = k - TWOH, i = e >> 3, g = e & 7;
            v = k1s[(o * TWOH + i) * 8 + g] * k1c[o * TWOH + i];
        }
        __nv_bfloat16 h, l; split_bf16(v, h, l);
        g_W1h[idx] = h; g_W1l[idx] = l;
        return;
    }
    idx -= N1;
    {
        int o = idx / KF_PAD, k = idx % KF_PAD;
        if (o < IN_F) {
            if (k < TWOH) v = k2b[o * TWOH + k];
            else if (k < 720) {
                int e = k - TWOH, i = e >> 3, g = e & 7;
                v = k2s[(o * TWOH + i) * 8 + g] * k2c[o * TWOH + i];
            }
        }
        __nv_bfloat16 h, l; split_bf16(v, h, l);
        g_W2h[idx] = h; g_W2l[idx] = l;
    }
}

// ---------------- KAN feature expansion (R7 version — measured best) ----------------
__device__ __forceinline__ float gridv(int j) { return 0.4f * (float)(j - 3) - 1.0f; }

__global__ void expand_feat(const float* __restrict__ X, int total)
{
    int idx = blockIdx.x * blockDim.x + threadIdx.x;
    if (idx >= total) return;
    int n = idx / TWOH;
    int i = idx % TWOH;
    float x = X[idx];

    float su = x / (1.0f + expf(-x));
    {
        __nv_bfloat16 h, l; split_bf16(su, h, l);
        g_fhi[(size_t)n * KF_PAD + i] = h;
        g_flo[(size_t)n * KF_PAD + i] = l;
    }

    float bset[11];
#pragma unroll
    for (int j = 0; j < 11; j++)
        bset[j] = (x >= gridv(j) && x < gridv(j + 1)) ? 1.0f : 0.0f;
#pragma unroll
    for (int j = 0; j < 10; j++)
        bset[j] = (x - gridv(j)) * 2.5f * bset[j] + (gridv(j + 2) - x) * 2.5f * bset[j + 1];
#pragma unroll
    for (int j = 0; j < 9; j++)
        bset[j] = (x - gridv(j)) * 1.25f * bset[j] + (gridv(j + 3) - x) * 1.25f * bset[j + 1];
#pragma unroll
    for (int j = 0; j < 8; j++)
        bset[j] = (x - gridv(j)) * (1.0f / 1.2f) * bset[j] + (gridv(j + 4) - x) * (1.0f / 1.2f) * bset[j + 1];

    union { __nv_bfloat16 b[8]; uint4 u; } hv, lv;
#pragma unroll
    for (int j = 0; j < 8; j++) split_bf16(bset[j], hv.b[j], lv.b[j]);
    *(uint4*)&g_fhi[(size_t)n * KF_PAD + TWOH + i * 8] = hv.u;
    *(uint4*)&g_flo[(size_t)n * KF_PAD + TWOH + i * 8] = lv.u;
}

// ---------------- N-fused HMMA GEMM: one CTA covers M=64 x (NCNT*N_SUB) ----------------
// A loaded once per K-chunk and reused across all NCNT N-groups.
// A double-buffered over kc; B double-buffered over the (kc,ny) sequence.
// EPI 0: plain y1   EPI 1: gates scatter+bias (ny = dir)   EPI 2: kan2 sigmoid
template <int N_SUB>
struct TM {
    static constexpr int N128   = N_SUB * 128;
    static constexpr int A_ST   = 16384;          // per stage: hi 8K + lo 8K
    static constexpr int OFF_B  = 32768;
    static constexpr int B_BUF  = 2 * N128;       // hi + lo
    static constexpr int TOTAL  = 32768 + 2 * B_BUF;
};

template <int N_SUB, int NCNT, int EPI, int KPAD, int NCHUNK>
__global__ __launch_bounds__(128) void hgemm_multi(
    const __nv_bfloat16* __restrict__ Ahi, const __nv_bfloat16* __restrict__ Alo,
    const __nv_bfloat16* __restrict__ BhiAll, const __nv_bfloat16* __restrict__ BloAll,
    const float* __restrict__ biasF, const float* __restrict__ biasB,
    float* __restrict__ outP, const float* __restrict__ slope)
{
    constexpr int NT8 = N_SUB / 8;
    extern __shared__ __align__(128) char smem[];
    const uint32_t smemB = smem_to_u32(smem);
    const int tid = threadIdx.x, wid = tid >> 5, lid = tid & 31;
    const size_t aRow0 = (size_t)blockIdx.x * 64;

    float acc[NCNT][NT8][4];
#pragma unroll
    for (int y = 0; y < NCNT; y++)
#pragma unroll
        for (int t = 0; t < NT8; t++)
#pragma unroll
            for (int j = 0; j < 4; j++) acc[y][t][j] = 0.0f;

    const int rwA = wid * 16 + (lid & 15);
    const int khA = lid >> 4;
    const int bTs = (lid >> 4) & 1, bKh = (lid >> 3) & 1, bRow = lid & 7;

    auto loadA = [&](int kc, int st) {
        const int kOff = kc << 6;
        const uint32_t base = smemB + st * TM<N_SUB>::A_ST;
#pragma unroll
        for (int j = 0; j < 4; j++) {
            int s = j * 128 + tid;
            int r = s >> 3, c = s & 7;
            size_t go = (aRow0 + r) * (size_t)KPAD + kOff + c * 8;
            uint32_t sw = SMEM_SWIZZLE_128B((uint32_t)(r * 128 + c * 16));
            cp16(base + sw, Ahi + go);
            cp16(base + 8192 + sw, Alo + go);
        }
    };
    auto loadB = [&](int kc, int ny, int nb) {
        const int kOff = kc << 6;
        const __nv_bfloat16* Bhi = BhiAll + (size_t)ny * N_SUB * KPAD;
        const __nv_bfloat16* Blo = BloAll + (size_t)ny * N_SUB * KPAD;
        const uint32_t base = smemB + TM<N_SUB>::OFF_B + nb * TM<N_SUB>::B_BUF;
        for (int s = tid; s < N_SUB * 8; s += 128) {
            int r = s >> 3, c = s & 7;
            size_t go = (size_t)r * KPAD + kOff + c * 8;
            uint32_t sw = SMEM_SWIZZLE_128B((uint32_t)(r * 128 + c * 16));
            cp16(base + sw, Bhi + go);
            cp16(base + TM<N_SUB>::N128 + sw, Blo + go);
        }
    };

    loadA(0, 0);
    loadB(0, 0, 0);
    CP_COMMIT();

    for (int kc = 0; kc < NCHUNK; kc++) {
#pragma unroll
        for (int ny = 0; ny < NCNT; ny++) {
            const int it = kc * NCNT + ny;
            // prefetch next (kc2, ny2)
            if (it + 1 < NCHUNK * NCNT) {
                constexpr int NY2C = 1;  // (compile-time helper below)
                int ny2 = (ny + 1 == NCNT) ? 0 : ny + 1;
                int kc2 = (ny + 1 == NCNT) ? kc + 1 : kc;
                if (ny2 == 0) loadA(kc2, kc2 & 1);
                loadB(kc2, ny2, (it + 1) & 1);
                (void)NY2C;
            }
            CP_COMMIT();
            CP_WAIT1();
            __syncthreads();

            const uint32_t aBase = smemB + (kc & 1) * TM<N_SUB>::A_ST;
            const uint32_t bBase = smemB + TM<N_SUB>::OFF_B + (it & 1) * TM<N_SUB>::B_BUF;
            const uint32_t aHiB = aBase, aLoB = aBase + 8192;
            const uint32_t bHiB = bBase, bLoB = bBase + TM<N_SUB>::N128;

#pragma unroll
            for (int ks = 0; ks < 4; ks++) {
                uint32_t ah[4], al[4];
                uint32_t offA = SMEM_SWIZZLE_128B((uint32_t)(rwA * 128 + ks * 32 + khA * 16));
                ldsm_x4(ah, aHiB + offA);
                ldsm_x4(al, aLoB + offA);
#pragma unroll
                for (int nt = 0; nt < NT8; nt += 2) {
                    uint32_t bh[4], bl[4];
                    if (nt + 1 < NT8) {
                        int n = (nt + bTs) * 8 + bRow;
                        uint32_t off = SMEM_SWIZZLE_128B((uint32_t)(n * 128 + ks * 32 + bKh * 16));
                        ldsm_x4(bh, bHiB + off);
                        ldsm_x4(bl, bLoB + off);
                    } else {
                        int n = nt * 8 + bRow;
                        uint32_t off = SMEM_SWIZZLE_128B((uint32_t)(n * 128 + ks * 32 + bKh * 16));
                        ldsm_x2(bh, bHiB + off);
                        ldsm_x2(bl, bLoB + off);
                    }
                    mma_bf16(acc[ny][nt], ah, bh);
                    mma_bf16(acc[ny][nt], al, bh);
                    mma_bf16(acc[ny][nt], ah, bl);
                    if (nt + 1 < NT8) {
                        mma_bf16(acc[ny][nt + 1], ah, bh + 2);
                        mma_bf16(acc[ny][nt + 1], al, bh + 2);
                        mma_bf16(acc[ny][nt + 1], ah, bl + 2);
                    }
                }
            }
            __syncthreads();
        }
    }

    // ---- epilogue ----
    const int rr = (int)aRow0 + wid * 16 + (lid >> 2);
    const int cO = 2 * (lid & 3);
    if (EPI == 0) {
#pragma unroll
        for (int t = 0; t < NT8; t++) {
            int cb = t * 8 + cO;
            float* o0 = outP + (size_t)rr * TWOH + cb;
            float* o1 = outP + (size_t)(rr + 8) * TWOH + cb;
            o0[0] = acc[0][t][0]; o0[1] = acc[0][t][1];
            o1[0] = acc[0][t][2]; o1[1] = acc[0][t][3];
        }
    } else if (EPI == 1) {
        int b0 = rr / T_STEPS, t0 = rr % T_STEPS;
        int b1 = (rr + 8) / T_STEPS, t1 = (rr + 8) % T_STEPS;
#pragma unroll
        for (int y = 0; y < NCNT; y++) {
            float* baseO = y ? g_giB : g_giF;
            const float* bia = y ? biasB : biasF;
            float* d0 = baseO + ((size_t)t0 * BATCH + b0) * G3H;
            float* d1 = baseO + ((size_t)t1 * BATCH + b1) * G3H;
#pragma unroll
            for (int t = 0; t < NT8; t++) {
                int cb = t * 8 + cO;
                d0[cb]     = acc[y][t][0] + bia[cb];
                d0[cb + 1] = acc[y][t][1] + bia[cb + 1];
                d1[cb]     = acc[y][t][2] + bia[cb];
                d1[cb + 1] = acc[y][t][3] + bia[cb + 1];
            }
        }
    } else {
#pragma unroll
        for (int y = 0; y < NCNT; y++) {
            const int cbase = y * 88;
#pragma unroll
            for (int t = 0; t < NT8; t++) {
                int cb = cbase + t * 8 + cO;
#pragma unroll
                for (int j = 0; j < 2; j++) {
                    int cg = cb + j;
                    if (cg < IN_F) {
                        outP[(size_t)rr * IN_F + cg] =
                            1.2f / (1.0f + expf(-slope[cg] * acc[y][t][j]));
                        outP[(size_t)(rr + 8) * IN_F + cg] =
                            1.2f / (1.0f + expf(-slope[cg] * acc[y][t][2 + j]));
                    }
                }
            }
        }
    }
}

// ---------------- GRU helpers ----------------
__device__ __forceinline__ float sigm_fast(float x) {
    float e = __expf(-x);
    return __fdividef(1.0f, 1.0f + e);
}
__device__ __forceinline__ float tanh_fast(float x) {
    float e = __expf(2.0f * x);
    return 1.0f - __fdividef(2.0f, 1.0f + e);
}

// ---------------- GRU scan (R7 version: 320 threads, 1 barrier/step) ----------------
__global__ __launch_bounds__(320) void gru_scan2(
    const float* __restrict__ WhhF0, const float* __restrict__ bhhF0,
    const float* __restrict__ WihF1, const float* __restrict__ WhhF1,
    const float* __restrict__ bihF1, const float* __restrict__ bhhF1,
    const float* __restrict__ WhhB0, const float* __restrict__ bhhB0,
    const float* __restrict__ WihB1, const float* __restrict__ WhhB1,
    const float* __restrict__ bihB1, const float* __restrict__ bhhB1)
{
    const int b   = blockIdx.x;
    const int dir = blockIdx.y;
    const float* Whh0 = dir ? WhhB0 : WhhF0;
    const float* bhh0 = dir ? bhhB0 : bhhF0;
    const float* W1ih = dir ? WihB1 : WihF1;
    const float* W1hh = dir ? WhhB1 : WhhF1;
    const float* b1ih = dir ? bihB1 : bihF1;
    const float* b1hh = dir ? bhhB1 : bhhF1;
    const float* gi   = dir ? g_giB : g_giF;
    float* out = g_hcat + (size_t)b * T_STEPS * TWOH + dir * HID;

    __shared__ float s_h0[2][HID];
    __shared__ float s_h1[2][HID];

    const int tid = threadIdx.x;
    const bool isA = tid < 160;
    const int lane = isA ? tid : tid - 160;
    const int unit = lane >> 2;
    const int q    = lane & 3;
    const int k0   = q * 10;

    float wA[3][10];
    float wI[3][10], wH[3][10];
    float brz0 = 0.f, brz1 = 0.f, bn0 = 0.f;
    float bR = 0.f, bZ = 0.f, bIN = 0.f, bHN = 0.f;
    if (isA) {
#pragma unroll
        for (int g = 0; g < 3; g++)
#pragma unroll
            for (int k = 0; k < 10; k++)
                wA[g][k] = Whh0[(g * HID + unit) * HID + k0 + k];
        brz0 = bhh0[unit];
        brz1 = bhh0[HID + unit];
        bn0  = bhh0[2 * HID + unit];
    } else {
#pragma unroll
        for (int g = 0; g < 3; g++)
#pragma unroll
            for (int k = 0; k < 10; k++) {
                wI[g][k] = W1ih[(g * HID + unit) * HID + k0 + k];
                wH[g][k] = W1hh[(g * HID + unit) * HID + k0 + k];
            }
        bR  = b1ih[unit]           + b1hh[unit];
        bZ  = b1ih[HID + unit]     + b1hh[HID + unit];
        bIN = b1ih[2 * HID + unit];
        bHN = b1hh[2 * HID + unit];
    }

    if (tid < HID) { s_h0[0][tid] = 0.0f; s_h0[1][tid] = 0.0f;
                     s_h1[0][tid] = 0.0f; s_h1[1][tid] = 0.0f; }

    float gc0 = 0.f, gc1 = 0.f, gc2 = 0.f;
    if (isA) {
        int grow = dir ? (T_STEPS - 1) : 0;
        const float* gp = gi + ((size_t)grow * BATCH + b) * G3H;
        gc0 = gp[unit]; gc1 = gp[HID + unit]; gc2 = gp[2 * HID + unit];
    }
    __syncthreads();

    for (int s = 0; s <= T_STEPS; s++) {
        const int cur = s & 1, nxt = (s & 1) ^ 1;
        float gn0 = 0.f, gn1 = 0.f, gn2 = 0.f;

        if (isA) {
            if (s + 1 < T_STEPS) {
                int grow = dir ? (T_STEPS - 2 - s) : (s + 1);
                const float* gp = gi + ((size_t)grow * BATCH + b) * G3H;
                gn0 = gp[unit]; gn1 = gp[HID + unit]; gn2 = gp[2 * HID + unit];
            }
            if (s < T_STEPS) {
                const float* h0c = s_h0[cur];
                float hk[10];
                {
                    const float2* h2 = (const float2*)(h0c + k0);
#pragma unroll
                    for (int k = 0; k < 5; k++) {
                        float2 v = h2[k];
                        hk[2 * k] = v.x; hk[2 * k + 1] = v.y;
                    }
                }
                float p0 = 0.f, p1 = 0.f, p2 = 0.f;
#pragma unroll
                for (int k = 0; k < 10; k++) {
                    p0 = fmaf(wA[0][k], hk[k], p0);
                    p1 = fmaf(wA[1][k], hk[k], p1);
                    p2 = fmaf(wA[2][k], hk[k], p2);
                }
                p0 += __shfl_xor_sync(0xffffffffu, p0, 1);
                p0 += __shfl_xor_sync(0xffffffffu, p0, 2);
                p1 += __shfl_xor_sync(0xffffffffu, p1, 1);
                p1 += __shfl_xor_sync(0xffffffffu, p1, 2);
                p2 += __shfl_xor_sync(0xffffffffu, p2, 1);
                p2 += __shfl_xor_sync(0xffffffffu, p2, 2);
                float r = sigm_fast(gc0 + p0 + brz0);
                float z = sigm_fast(gc1 + p1 + brz1);
                float n = tanh_fast(gc2 + r * (p2 + bn0));
                float hnew = (1.0f - z) * n + z * h0c[unit];
                if (q == 0) s_h0[nxt][unit] = hnew;
            }
        } else {
            if (s >= 1) {
                const float* h0c = s_h0[cur];
                const float* h1c = s_h1[cur];
                float a[10], hh[10];
                {
                    const float2* a2 = (const float2*)(h0c + k0);
                    const float2* b2 = (const float2*)(h1c + k0);
#pragma unroll
                    for (int k = 0; k < 5; k++) {
                        float2 va = a2[k], vb = b2[k];
                        a[2 * k] = va.x; a[2 * k + 1] = va.y;
                        hh[2 * k] = vb.x; hh[2 * k + 1] = vb.y;
                    }
                }
                float pr = 0.f, pz = 0.f, pin = 0.f, phn = 0.f;
#pragma unroll
                for (int k = 0; k < 10; k++) {
                    pr  = fmaf(wI[0][k], a[k], pr);
                    pz  = fmaf(wI[1][k], a[k], pz);
                    pin = fmaf(wI[2][k], a[k], pin);
                    phn = fmaf(wH[2][k], hh[k], phn);
                }
#pragma unroll
                for (int k = 0; k < 10; k++) {
                    pr = fmaf(wH[0][k], hh[k], pr);
                    pz = fmaf(wH[1][k], hh[k], pz);
                }
                pr  += __shfl_xor_sync(0xffffffffu, pr, 1);
                pr  += __shfl_xor_sync(0xffffffffu, pr, 2);
                pz  += __shfl_xor_sync(0xffffffffu, pz, 1);
                pz  += __shfl_xor_sync(0xffffffffu, pz, 2);
                pin += __shfl_xor_sync(0xffffffffu, pin, 1);
                pin += __shfl_xor_sync(0xffffffffu, pin, 2);
                phn += __shfl_xor_sync(0xffffffffu, phn, 1);
                phn += __shfl_xor_sync(0xffffffffu, phn, 2);
                float r = sigm_fast(pr + bR);
                float z = sigm_fast(pz + bZ);
                float n = tanh_fast(pin + bIN + r * (phn + bHN));
                float h = (1.0f - z) * n + z * h1c[unit];
                if (q == 0) {
                    s_h1[nxt][unit] = h;
                    out[(size_t)(s - 1) * TWOH + unit] = h;
                }
            }
        }
        __syncthreads();
        gc0 = gn0; gc1 = gn1; gc2 = gn2;
    }
}

// ---------------- launch ----------------
extern "C" void kernel_launch(void* const* d_in, const int* in_sizes, int n_in,
                              void* d_out, int out_size)
{
    const float* x     = (const float*)d_in[0];
    const float* f0Wih = (const float*)d_in[2];
    const float* f0Whh = (const float*)d_in[3];
    const float* f0bih = (const float*)d_in[4];
    const float* f0bhh = (const float*)d_in[5];
    const float* f1Wih = (const float*)d_in[6];
    const float* f1Whh = (const float*)d_in[7];
    const float* f1bih = (const float*)d_in[8];
    const float* f1bhh = (const float*)d_in[9];
    const float* b0Wih = (const float*)d_in[10];
    const float* b0Whh = (const float*)d_in[11];
    const float* b0bih = (const float*)d_in[12];
    const float* b0bhh = (const float*)d_in[13];
    const float* b1Wih = (const float*)d_in[14];
    const float* b1Whh = (const float*)d_in[15];
    const float* b1bih = (const float*)d_in[16];
    const float* b1bhh = (const float*)d_in[17];
    const float* k1b   = (const float*)d_in[18];
    const float* k1s   = (const float*)d_in[19];
    const float* k1c   = (const float*)d_in[20];
    const float* k2b   = (const float*)d_in[21];
    const float* k2s   = (const float*)d_in[22];
    const float* k2c   = (const float*)d_in[23];
    const float* slope = (const float*)d_in[24];
    float* out = (float*)d_out;

    __nv_bfloat16 *p_xhi, *p_xlo, *p_fhi, *p_flo, *p_Wgh, *p_Wgl, *p_W1h, *p_W1l, *p_W2h, *p_W2l;
    float *p_hcat, *p_y1;
    cudaGetSymbolAddress((void**)&p_xhi, g_xhi);
    cudaGetSymbolAddress((void**)&p_xlo, g_xlo);
    cudaGetSymbolAddress((void**)&p_fhi, g_fhi);
    cudaGetSymbolAddress((void**)&p_flo, g_flo);
    cudaGetSymbolAddress((void**)&p_Wgh, g_Wgh);
    cudaGetSymbolAddress((void**)&p_Wgl, g_Wgl);
    cudaGetSymbolAddress((void**)&p_W1h, g_W1h);
    cudaGetSymbolAddress((void**)&p_W1l, g_W1l);
    cudaGetSymbolAddress((void**)&p_W2h, g_W2h);
    cudaGetSymbolAddress((void**)&p_W2l, g_W2l);
    cudaGetSymbolAddress((void**)&p_hcat, g_hcat);
    cudaGetSymbolAddress((void**)&p_y1, g_y1);

    cudaFuncSetAttribute((const void*)hgemm_multi<120, 2, 1, KX_PAD, 5>,
                         cudaFuncAttributeMaxDynamicSharedMemorySize, TM<120>::TOTAL);
    cudaFuncSetAttribute((const void*)hgemm_multi<80, 1, 0, KF_PAD, 12>,
                         cudaFuncAttributeMaxDynamicSharedMemorySize, TM<80>::TOTAL);
    cudaFuncSetAttribute((const void*)hgemm_multi<88, 3, 2, KF_PAD, 12>,
                         cudaFuncAttributeMaxDynamicSharedMemorySize, TM<88>::TOTAL);

    // 1. conversions
    conv_x<<<(NTOK * KX_PAD + 255) / 256, 256>>>(x);
    {
        int total = 2 * G3H * KX_PAD + TWOH * KF_PAD + 264 * KF_PAD;
        pack_weights<<<(total + 255) / 256, 256>>>(f0Wih, b0Wih, k1b, k1s, k1c, k2b, k2s, k2c);
    }
    // 2. layer-0 input gates: both dirs fused in one CTA (A loaded once)
    {
        hgemm_multi<120, 2, 1, KX_PAD, 5><<<NTOK / 64, 128, TM<120>::TOTAL>>>(
            p_xhi, p_xlo, p_Wgh, p_Wgl, f0bih, b0bih, nullptr, nullptr);
    }
    // 3. GRU scan (R7 version — measured best)
    {
        dim3 grid(BATCH, 2);
        gru_scan2<<<grid, 320>>>(f0Whh, f0bhh, f1Wih, f1Whh, f1bih, f1bhh,
                                 b0Whh, b0bhh, b1Wih, b1Whh, b1bih, b1bhh);
    }
    // 4. KAN layer 1: expand + GEMM
    {
        expand_feat<<<(NTOK * TWOH + 255) / 256, 256>>>(p_hcat, NTOK * TWOH);
        hgemm_multi<80, 1, 0, KF_PAD, 12><<<NTOK / 64, 128, TM<80>::TOTAL>>>(
            p_fhi, p_flo, p_W1h, p_W1l, nullptr, nullptr, p_y1, nullptr);
    }
    // 5. KAN layer 2: expand + N-fused GEMM (A loaded once instead of 3x) + sigmoid
    {
        expand_feat<<<(NTOK * TWOH + 255) / 256, 256>>>(p_y1, NTOK * TWOH);
        hgemm_multi<88, 3, 2, KF_PAD, 12><<<NTOK / 64, 128, TM<88>::TOTAL>>>(
            p_fhi, p_flo, p_W2h, p_W2l, nullptr, nullptr, out, slope);
    }
    (void)in_sizes; (void)n_in; (void)out_size;
}